// round 3
// baseline (speedup 1.0000x reference)
#include <cuda_runtime.h>

#define NHEADS 8
#define HDIM   64
#define TNUM   10
#define QDIM   256
#define NCOLS  80        // NHEADS * TNUM
#define NBATCH 131072

#define BM  128
#define BK  32
#define TPB 256

// Precomputed fused projection matrix: M[c][col], col = h*10 + t.
// scores[h,n,t] = sum_c X[n,c] * M[c][h*10+t]   (1/sqrt(64) folded in)
__device__ float M_g[QDIM * NCOLS];

__global__ void precompute_M(const float* __restrict__ embed,
                             const float* __restrict__ Wq,
                             const float* __restrict__ Wk) {
    const int col = blockIdx.x;          // 0..79
    const int h = col / TNUM;
    const int t = col % TNUM;
    __shared__ float kv[HDIM];
    const int tid = threadIdx.x;         // 0..255
    if (tid < HDIM) {
        const int e = h * HDIM + tid;
        float s = 0.f;
        #pragma unroll
        for (int d = 0; d < HDIM; ++d)
            s += tanhf(embed[t * HDIM + d]) * Wk[e * HDIM + d];
        kv[tid] = s;
    }
    __syncthreads();
    float s = 0.f;
    #pragma unroll
    for (int dd = 0; dd < HDIM; ++dd)
        s += Wq[(h * HDIM + dd) * QDIM + tid] * kv[dd];
    M_g[tid * NCOLS + col] = s * 0.125f;
}

// ---- packed f32x2 helpers (FFMA2: 2x fp32 FMA throughput on sm_103a) ----
__device__ __forceinline__ unsigned long long splat2(float x) {
    unsigned long long r;
    asm("mov.b64 %0, {%1, %1};" : "=l"(r) : "r"(__float_as_uint(x)));
    return r;
}
__device__ __forceinline__ void fma2(unsigned long long& d,
                                     unsigned long long a,
                                     unsigned long long b) {
    asm("fma.rn.f32x2 %0, %1, %2, %0;" : "+l"(d) : "l"(a), "l"(b));
}
__device__ __forceinline__ float2 unpack2(unsigned long long v) {
    float lo, hi;
    asm("mov.b64 {%0, %1}, %2;" : "=f"(lo), "=f"(hi) : "l"(v));
    return make_float2(lo, hi);
}

__global__ __launch_bounds__(TPB, 2)
void fused_attn(const float* __restrict__ X,
                const float* __restrict__ embed,
                float* __restrict__ style,   // [N][512]
                float* __restrict__ attn)    // [8][N][10]
{
    // A: [row][k], pitch 33 -> conflict-free scalar reads (8-way broadcast)
    __shared__ __align__(16) float A_sh[BM][BK + 1];
    // M: [k][8 groups of 20 floats]; group g holds cols g*10..g*10+9
    //    group pitch 20 floats (80B) -> conflict-free LDS.128 across cg
    __shared__ __align__(16) float M_sh[BK][160];
    __shared__ __align__(16) float kr_sh[TNUM * HDIM];

    const int tid = threadIdx.x;
    const int rg = tid >> 3;     // 0..31 : 4 rows each
    const int cg = tid & 7;      // 0..7  : head / 10-col group
    const int rowBase = blockIdx.x * BM;

    for (int i = tid; i < TNUM * HDIM; i += TPB)
        kr_sh[i] = tanhf(embed[i]);

    unsigned long long acc[4][5];   // 4 rows x 5 col-pairs (10 cols)
    #pragma unroll
    for (int r = 0; r < 4; ++r)
        #pragma unroll
        for (int j = 0; j < 5; ++j)
            acc[r][j] = 0ull;

    for (int k0 = 0; k0 < QDIM; k0 += BK) {
        __syncthreads();
        // A tile: 128 rows x 32 k, 4 x float4 per thread, coalesced
        #pragma unroll
        for (int j = 0; j < 4; ++j) {
            const int v = tid + TPB * j;
            const int row = v >> 3;
            const int ks = v & 7;
            const float4 a = *(const float4*)(X + (size_t)(rowBase + row) * QDIM + k0 + ks * 4);
            A_sh[row][ks * 4 + 0] = a.x;
            A_sh[row][ks * 4 + 1] = a.y;
            A_sh[row][ks * 4 + 2] = a.z;
            A_sh[row][ks * 4 + 3] = a.w;
        }
        // M tile: 32 k x 80 cols into grouped layout (L2-resident source)
        #pragma unroll
        for (int j = 0; j < 10; ++j) {
            const int v = tid + TPB * j;           // 0..2559
            const int kk = v / NCOLS;
            const int c = v - kk * NCOLS;
            M_sh[kk][(c / 10) * 20 + (c % 10)] = M_g[(k0 + kk) * NCOLS + c];
        }
        __syncthreads();

        #pragma unroll
        for (int kk = 0; kk < BK; ++kk) {
            const ulonglong2 m01 = *(const ulonglong2*)&M_sh[kk][cg * 20];
            const ulonglong2 m23 = *(const ulonglong2*)&M_sh[kk][cg * 20 + 4];
            const unsigned long long m4 = *(const unsigned long long*)&M_sh[kk][cg * 20 + 8];
            #pragma unroll
            for (int r = 0; r < 4; ++r) {
                const unsigned long long a2 = splat2(A_sh[rg * 4 + r][kk]);
                fma2(acc[r][0], a2, m01.x);
                fma2(acc[r][1], a2, m01.y);
                fma2(acc[r][2], a2, m23.x);
                fma2(acc[r][3], a2, m23.y);
                fma2(acc[r][4], a2, m4);
            }
        }
    }

    // unpack scores
    float s[4][10];
    #pragma unroll
    for (int r = 0; r < 4; ++r)
        #pragma unroll
        for (int j = 0; j < 5; ++j) {
            const float2 f = unpack2(acc[r][j]);
            s[r][2 * j]     = f.x;
            s[r][2 * j + 1] = f.y;
        }

    // attn_score: [h][n][t], h == cg, contiguous 10 floats per (h,n)
    #pragma unroll
    for (int r = 0; r < 4; ++r) {
        const size_t n = (size_t)rowBase + rg * 4 + r;
        float2* p = (float2*)(attn + (size_t)cg * NBATCH * TNUM + n * TNUM);
        #pragma unroll
        for (int j = 0; j < 5; ++j)
            p[j] = make_float2(s[r][2 * j], s[r][2 * j + 1]);
    }

    // style epilogue: out[n, cg*64 + d] = sum_t s[r][t] * kr[t][d]
    #pragma unroll
    for (int r = 0; r < 4; ++r) {
        const size_t n = (size_t)rowBase + rg * 4 + r;
        unsigned long long s2[10];
        #pragma unroll
        for (int t = 0; t < TNUM; ++t) s2[t] = splat2(s[r][t]);
        float* outp = style + n * 512 + cg * 64;
        #pragma unroll
        for (int dc = 0; dc < 8; ++dc) {        // 8-float chunks of d
            unsigned long long o[4] = {0ull, 0ull, 0ull, 0ull};
            #pragma unroll
            for (int t = 0; t < TNUM; ++t) {
                const ulonglong2 ka = *(const ulonglong2*)&kr_sh[t * HDIM + dc * 8];
                const ulonglong2 kb = *(const ulonglong2*)&kr_sh[t * HDIM + dc * 8 + 4];
                fma2(o[0], s2[t], ka.x);
                fma2(o[1], s2[t], ka.y);
                fma2(o[2], s2[t], kb.x);
                fma2(o[3], s2[t], kb.y);
            }
            const float2 f0 = unpack2(o[0]), f1 = unpack2(o[1]);
            const float2 f2 = unpack2(o[2]), f3 = unpack2(o[3]);
            *(float4*)(outp + dc * 8)     = make_float4(f0.x, f0.y, f1.x, f1.y);
            *(float4*)(outp + dc * 8 + 4) = make_float4(f2.x, f2.y, f3.x, f3.y);
        }
    }
}

extern "C" void kernel_launch(void* const* d_in, const int* in_sizes, int n_in,
                              void* d_out, int out_size) {
    (void)in_sizes; (void)n_in; (void)out_size;
    const float* X     = (const float*)d_in[0];
    const float* embed = (const float*)d_in[1];
    const float* Wq    = (const float*)d_in[2];
    const float* Wk    = (const float*)d_in[3];

    float* style = (float*)d_out;                              // N*512 floats
    float* attn  = (float*)d_out + (size_t)NBATCH * 512;       // 8*N*10 floats

    precompute_M<<<NCOLS, 256>>>(embed, Wq, Wk);
    fused_attn<<<NBATCH / BM, TPB>>>(X, embed, style, attn);
}